// round 15
// baseline (speedup 1.0000x reference)
#include <cuda_runtime.h>
#include <cuda_fp16.h>
#include <cstdint>
#include <math.h>

#define NN 50000
#define NE 800000
#define NG 128
#define DIM 128
#define NCLS 10
#define SCAN_BLOCKS 196   // ceil(50000/256)
#define HALF_ROWS 25088   // 128-aligned split point

// ---------------- device scratch ----------------
__device__ __align__(16) __half g_hA[NN * DIM];
__device__ __align__(16) __half g_hB[NN * DIM];
__device__ __align__(16) __half g_acc16[NN * DIM];
__device__ float g_invdeg[NN];
__device__ int g_deg[NN];
__device__ int g_rowptr[NN + 1];
__device__ int g_cursor[NN];
__device__ int g_csr[NE];
__device__ int g_bsum[SCAN_BLOCKS];
__device__ int g_bpre[SCAN_BLOCKS];
// weights transposed+concat fp16 (1-term): [layer][n=128][k=256]
__device__ __align__(16) __half g_Bt[3 * DIM * 2 * DIM];

// ---------------- helpers ----------------
__device__ __forceinline__ uint32_t smem_u32(const void* p) {
    return (uint32_t)__cvta_generic_to_shared((void*)p);
}
__device__ __forceinline__ uint32_t swz(uint32_t x) { return x ^ (((x) >> 3) & 0x70); }

__device__ __forceinline__ void cpa16(uint32_t dst, const void* src, int sz) {
    asm volatile("cp.async.cg.shared.global [%0], [%1], 16, %2;"
                 :: "r"(dst), "l"(src), "r"(sz) : "memory");
}
#define CP_COMMIT() asm volatile("cp.async.commit_group;" ::: "memory")
#define CP_WAIT(n) asm volatile("cp.async.wait_group %0;" :: "n"(n) : "memory")

__device__ __forceinline__ void ldmx4(uint32_t* r, uint32_t a) {
    asm volatile("ldmatrix.sync.aligned.m8n8.x4.shared.b16 {%0,%1,%2,%3}, [%4];"
                 : "=r"(r[0]), "=r"(r[1]), "=r"(r[2]), "=r"(r[3]) : "r"(a));
}
__device__ __forceinline__ void mma16816(float* c, const uint32_t* a, uint32_t b0,
                                         uint32_t b1) {
    asm volatile(
        "mma.sync.aligned.m16n8k16.row.col.f32.f16.f16.f32 "
        "{%0,%1,%2,%3}, {%4,%5,%6,%7}, {%8,%9}, {%0,%1,%2,%3};"
        : "+f"(c[0]), "+f"(c[1]), "+f"(c[2]), "+f"(c[3])
        : "r"(a[0]), "r"(a[1]), "r"(a[2]), "r"(a[3]), "r"(b0), "r"(b1));
}

// ---------------- CSR build ----------------
__global__ void zero_int(int* p, int n) {
    int i = blockIdx.x * blockDim.x + threadIdx.x;
    if (i < n) p[i] = 0;
}
__global__ void hist_kernel(const int4* __restrict__ dst4, int* __restrict__ deg) {
    int tid = blockIdx.x * blockDim.x + threadIdx.x;
    if (tid >= NE / 8) return;
    int4 d0 = __ldg(&dst4[tid * 2]);
    int4 d1 = __ldg(&dst4[tid * 2 + 1]);
    atomicAdd(&deg[d0.x], 1); atomicAdd(&deg[d0.y], 1);
    atomicAdd(&deg[d0.z], 1); atomicAdd(&deg[d0.w], 1);
    atomicAdd(&deg[d1.x], 1); atomicAdd(&deg[d1.y], 1);
    atomicAdd(&deg[d1.z], 1); atomicAdd(&deg[d1.w], 1);
}
__global__ void __launch_bounds__(256)
scan1_kernel(const int* __restrict__ deg, int* __restrict__ bsum) {
    __shared__ int s[256];
    int t = threadIdx.x;
    int idx = blockIdx.x * 256 + t;
    s[t] = (idx < NN) ? deg[idx] : 0;
    __syncthreads();
#pragma unroll
    for (int off = 128; off > 0; off >>= 1) {
        if (t < off) s[t] += s[t + off];
        __syncthreads();
    }
    if (t == 0) bsum[blockIdx.x] = s[0];
}
__global__ void __launch_bounds__(256)
scan2_kernel(const int* __restrict__ bsum, int* __restrict__ bpre,
             int* __restrict__ rowptr) {
    __shared__ int s[256];
    int t = threadIdx.x;
    int v = (t < SCAN_BLOCKS) ? bsum[t] : 0;
    s[t] = v;
    __syncthreads();
#pragma unroll
    for (int off = 1; off < 256; off <<= 1) {
        int u = (t >= off) ? s[t - off] : 0;
        __syncthreads();
        s[t] += u;
        __syncthreads();
    }
    if (t < SCAN_BLOCKS) bpre[t] = s[t] - v;
    if (t == 0) rowptr[NN] = NE;
}
__global__ void __launch_bounds__(256)
scan3_kernel(const int* __restrict__ deg, const int* __restrict__ bpre,
             int* __restrict__ rowptr, int* __restrict__ cursor,
             float* __restrict__ invdeg) {
    __shared__ int s[256];
    int t = threadIdx.x;
    int idx = blockIdx.x * 256 + t;
    int d = (idx < NN) ? deg[idx] : 0;
    s[t] = d;
    __syncthreads();
#pragma unroll
    for (int off = 1; off < 256; off <<= 1) {
        int u = (t >= off) ? s[t - off] : 0;
        __syncthreads();
        s[t] += u;
        __syncthreads();
    }
    if (idx < NN) {
        int pos = bpre[blockIdx.x] + s[t] - d;
        rowptr[idx] = pos;
        cursor[idx] = pos;
        invdeg[idx] = 1.0f / fmaxf((float)d, 1.0f);
    }
}
__global__ void fill_kernel(const int4* __restrict__ src4, const int4* __restrict__ dst4,
                            int* __restrict__ cursor, int* __restrict__ csr) {
    int tid = blockIdx.x * blockDim.x + threadIdx.x;
    if (tid >= NE / 8) return;
    int4 d0 = __ldg(&dst4[tid * 2]);
    int4 d1 = __ldg(&dst4[tid * 2 + 1]);
    int4 s0 = __ldg(&src4[tid * 2]);
    int4 s1 = __ldg(&src4[tid * 2 + 1]);
    const int dd[8] = {d0.x, d0.y, d0.z, d0.w, d1.x, d1.y, d1.z, d1.w};
    const int ss[8] = {s0.x, s0.y, s0.z, s0.w, s1.x, s1.y, s1.z, s1.w};
    int pos[8];
#pragma unroll
    for (int i = 0; i < 8; ++i) pos[i] = atomicAdd(&cursor[dd[i]], 1);
#pragma unroll
    for (int i = 0; i < 8; ++i) csr[pos[i]] = ss[i];
}

// ---------------- weight prep ----------------
__global__ void prep_w_all(const float* __restrict__ Ws0, const float* __restrict__ Wn0,
                           const float* __restrict__ Ws1, const float* __restrict__ Wn1,
                           const float* __restrict__ Ws2, const float* __restrict__ Wn2,
                           __half* __restrict__ Bt) {
    int i = blockIdx.x * blockDim.x + threadIdx.x;
    if (i >= 3 * DIM * 2 * DIM) return;
    int l = i / (DIM * 2 * DIM);
    int r = i - l * (DIM * 2 * DIM);
    int n = r >> 8;
    int k = r & 255;
    const float* Ws = (l == 0) ? Ws0 : (l == 1) ? Ws1 : Ws2;
    const float* Wn = (l == 0) ? Wn0 : (l == 1) ? Wn1 : Wn2;
    float w = (k < DIM) ? Ws[k * DIM + n] : Wn[(k - DIM) * DIM + n];
    Bt[i] = __float2half_rn(w);
}

// ---------------- features -> fp16 ----------------
__global__ void feat_to_h16(const float* __restrict__ f, __half* __restrict__ o) {
    int i = blockIdx.x * blockDim.x + threadIdx.x;
    if (i >= NN * DIM / 8) return;
    const float4* p = (const float4*)f + (size_t)i * 2;
    float4 a = p[0], b = p[1];
    uint4 v;
    __half2 t0 = __floats2half2_rn(a.x, a.y);
    __half2 t1 = __floats2half2_rn(a.z, a.w);
    __half2 t2 = __floats2half2_rn(b.x, b.y);
    __half2 t3 = __floats2half2_rn(b.z, b.w);
    v.x = *(uint32_t*)&t0; v.y = *(uint32_t*)&t1;
    v.z = *(uint32_t*)&t2; v.w = *(uint32_t*)&t3;
    *((uint4*)o + i) = v;
}

// ---------------- CSR gather over node range [base, endn) ----------------
__global__ void __launch_bounds__(256)
gather16_kernel(const __half* __restrict__ h16, const int* __restrict__ rowptr,
                const int* __restrict__ csr, const float* __restrict__ invdeg,
                __half* __restrict__ acc16, int base, int endn) {
    int node = base + blockIdx.x * 8 + (threadIdx.x >> 5);
    int lane = threadIdx.x & 31;
    if (node >= endn) return;
    int beg = __ldg(&rowptr[node]);
    int end = __ldg(&rowptr[node + 1]);
    float s0 = 0.f, s1 = 0.f, s2 = 0.f, s3 = 0.f;
    int i = beg;
    for (; i + 3 < end; i += 4) {
        int n0 = __ldg(&csr[i]), n1 = __ldg(&csr[i + 1]);
        int n2 = __ldg(&csr[i + 2]), n3 = __ldg(&csr[i + 3]);
        uint2 v0 = *(const uint2*)(h16 + (size_t)n0 * DIM + lane * 4);
        uint2 v1 = *(const uint2*)(h16 + (size_t)n1 * DIM + lane * 4);
        uint2 v2 = *(const uint2*)(h16 + (size_t)n2 * DIM + lane * 4);
        uint2 v3 = *(const uint2*)(h16 + (size_t)n3 * DIM + lane * 4);
#define ACC8(v)                                                     \
        {                                                           \
            float2 fa = __half22float2(*(__half2*)&(v).x);          \
            float2 fb = __half22float2(*(__half2*)&(v).y);          \
            s0 += fa.x; s1 += fa.y; s2 += fb.x; s3 += fb.y;         \
        }
        ACC8(v0) ACC8(v1) ACC8(v2) ACC8(v3)
    }
    for (; i < end; ++i) {
        int n0 = __ldg(&csr[i]);
        uint2 v0 = *(const uint2*)(h16 + (size_t)n0 * DIM + lane * 4);
        ACC8(v0)
    }
#undef ACC8
    float id = invdeg[node];
    __half2 o0 = __floats2half2_rn(s0 * id, s1 * id);
    __half2 o1 = __floats2half2_rn(s2 * id, s3 * id);
    uint2 o;
    o.x = *(uint32_t*)&o0; o.y = *(uint32_t*)&o1;
    *(uint2*)(acc16 + (size_t)node * DIM + lane * 4) = o;
}

// ---------------- fused SAGE GEMM over row range [rbase, NN) ----------------
#define SA 0
#define SB 16384
#define SMEM_BYTES 32768

__global__ void __launch_bounds__(256, 2)
sage_gemm(const __half* __restrict__ h16, const __half* __restrict__ acc16,
          const __half* __restrict__ Bt, const float* __restrict__ bias,
          __half* __restrict__ out16, int rbase) {
    extern __shared__ char sm[];
    const uint32_t sb = smem_u32(sm);
    const int t = threadIdx.x;
    const int lane = t & 31;
    const int wid = t >> 5;
    const int wm = wid & 3;
    const int wn = wid >> 2;
    const int row0 = rbase + blockIdx.x * 128;

    float cacc[2][8][4];
#pragma unroll
    for (int a = 0; a < 2; ++a)
#pragma unroll
        for (int b = 0; b < 8; ++b)
#pragma unroll
            for (int c = 0; c < 4; ++c) cacc[a][b][c] = 0.f;

    for (int kc = 0; kc < 4; ++kc) {
        {
            const __half* Asrc = (kc < 2) ? h16 : acc16;
            const int kbase = (kc & 1) * 64;
#pragma unroll
            for (int u = 0; u < 4; ++u) {
                int li = t + 256 * u;
                int row = li >> 3, seg = li & 7;
                int r = row0 + row;
                const void* g = Asrc + (size_t)r * DIM + kbase + seg * 8;
                cpa16(sb + SA + swz((uint32_t)(row * 128 + seg * 16)), g,
                      (r < NN) ? 16 : 0);
            }
#pragma unroll
            for (int u = 0; u < 4; ++u) {
                int li = t + 256 * u;
                int row = li >> 3, seg = li & 7;
                size_t gb = (size_t)row * 256 + kc * 64 + seg * 8;
                cpa16(sb + SB + swz((uint32_t)(row * 128 + seg * 16)), Bt + gb, 16);
            }
            CP_COMMIT();
        }
        CP_WAIT(0);
        __syncthreads();

#pragma unroll
        for (int ks = 0; ks < 4; ++ks) {
            uint32_t afr[2][4];
#pragma unroll
            for (int mt = 0; mt < 2; ++mt) {
                uint32_t row = wm * 32 + mt * 16 + (lane & 7) + ((lane >> 3) & 1) * 8;
                uint32_t cb = ks * 32 + ((lane >> 4) & 1) * 16;
                ldmx4(afr[mt], sb + SA + swz(row * 128 + cb));
            }
#pragma unroll
            for (int np = 0; np < 4; ++np) {
                uint32_t nrow = wn * 64 + np * 16 + (lane & 7) + ((lane >> 4) & 1) * 8;
                uint32_t cb = ks * 32 + ((lane >> 3) & 1) * 16;
                uint32_t bh[4];
                ldmx4(bh, sb + SB + swz(nrow * 128 + cb));
#pragma unroll
                for (int mt = 0; mt < 2; ++mt) {
                    mma16816(cacc[mt][2 * np], afr[mt], bh[0], bh[1]);
                    mma16816(cacc[mt][2 * np + 1], afr[mt], bh[2], bh[3]);
                }
            }
        }
        __syncthreads();
    }

#pragma unroll
    for (int mt = 0; mt < 2; ++mt) {
        int r0 = row0 + wm * 32 + mt * 16 + (lane >> 2);
#pragma unroll
        for (int nt = 0; nt < 8; ++nt) {
            int c = wn * 64 + nt * 8 + (lane & 3) * 2;
            float b0 = __ldg(&bias[c]);
            float b1 = __ldg(&bias[c + 1]);
            float* cc = cacc[mt][nt];
            if (r0 < NN) {
                __half2 hv = __floats2half2_rn(fmaxf(cc[0] + b0, 0.f),
                                               fmaxf(cc[1] + b1, 0.f));
                *(__half2*)(out16 + (size_t)r0 * DIM + c) = hv;
            }
            int r1 = r0 + 8;
            if (r1 < NN) {
                __half2 hv = __floats2half2_rn(fmaxf(cc[2] + b0, 0.f),
                                               fmaxf(cc[3] + b1, 0.f));
                *(__half2*)(out16 + (size_t)r1 * DIM + c) = hv;
            }
        }
    }
}

// ---------------- mean graph pooling + classifier head ----------------
__global__ void __launch_bounds__(512)
pool_kernel(const __half* __restrict__ h16, const int* __restrict__ gids,
            const float* __restrict__ Wf, const float* __restrict__ bf,
            float* __restrict__ out) {
    __shared__ float part[4][DIM];
    __shared__ float pooled[DIM];
    int g = blockIdx.x;
    int t = threadIdx.x;
    int nl = t >> 7;
    int col = t & 127;

    int lo = 0, hi = NN;
    while (lo < hi) { int m = (lo + hi) >> 1; if (__ldg(&gids[m]) < g) lo = m + 1; else hi = m; }
    int start = lo;
    lo = start; hi = NN;
    while (lo < hi) { int m = (lo + hi) >> 1; if (__ldg(&gids[m]) < g + 1) lo = m + 1; else hi = m; }
    int end = lo;

    float s = 0.f;
    for (int n = start + nl; n < end; n += 4)
        s += __half2float(h16[(size_t)n * DIM + col]);
    part[nl][col] = s;
    __syncthreads();

    if (nl == 0) {
        float cnt = fmaxf((float)(end - start), 1.0f);
        pooled[col] = (part[0][col] + part[1][col] + part[2][col] + part[3][col]) / cnt;
    }
    __syncthreads();

    if (t < NCLS) {
        float o = bf[t];
#pragma unroll 8
        for (int k = 0; k < DIM; ++k) o = fmaf(pooled[k], Wf[k * NCLS + t], o);
        out[g * NCLS + t] = o;
    }
}

// ---------------- launch (pipelined half-tiles over two streams) ----------------
static cudaStream_t g_side = 0;
static cudaEvent_t g_ev[16];
static bool g_res_init = false;

extern "C" void kernel_launch(void* const* d_in, const int* in_sizes, int n_in,
                              void* d_out, int out_size) {
    const float* feat = (const float*)d_in[0];
    const int* esrc = (const int*)d_in[1];
    const int* edst = (const int*)d_in[2];
    const int* gids = (const int*)d_in[3];
    const float* Ws[3] = {(const float*)d_in[4], (const float*)d_in[7], (const float*)d_in[10]};
    const float* Wn[3] = {(const float*)d_in[5], (const float*)d_in[8], (const float*)d_in[11]};
    const float* bs[3] = {(const float*)d_in[6], (const float*)d_in[9], (const float*)d_in[12]};
    const float* Wf = (const float*)d_in[13];
    const float* bf = (const float*)d_in[14];
    float* out = (float*)d_out;

    if (!g_res_init) {
        cudaStreamCreateWithFlags(&g_side, cudaStreamNonBlocking);
        for (int i = 0; i < 16; ++i)
            cudaEventCreateWithFlags(&g_ev[i], cudaEventDisableTiming);
        cudaFuncSetAttribute(sage_gemm, cudaFuncAttributeMaxDynamicSharedMemorySize,
                             SMEM_BYTES);
        g_res_init = true;
    }

    __half *hA, *hB, *acc16, *Bt;
    float* invdeg;
    int *deg, *rowptr, *cursor, *csr, *bsum, *bpre;
    cudaGetSymbolAddress((void**)&hA, g_hA);
    cudaGetSymbolAddress((void**)&hB, g_hB);
    cudaGetSymbolAddress((void**)&acc16, g_acc16);
    cudaGetSymbolAddress((void**)&invdeg, g_invdeg);
    cudaGetSymbolAddress((void**)&deg, g_deg);
    cudaGetSymbolAddress((void**)&rowptr, g_rowptr);
    cudaGetSymbolAddress((void**)&cursor, g_cursor);
    cudaGetSymbolAddress((void**)&csr, g_csr);
    cudaGetSymbolAddress((void**)&bsum, g_bsum);
    cudaGetSymbolAddress((void**)&bpre, g_bpre);
    cudaGetSymbolAddress((void**)&Bt, g_Bt);

    // fork: side stream branches off main
    cudaEventRecord(g_ev[0], 0);
    cudaStreamWaitEvent(g_side, g_ev[0], 0);

    // main: CSR build + invdeg chain
    zero_int<<<(NN + 255) / 256, 256>>>(deg, NN);
    hist_kernel<<<(NE / 8 + 255) / 256, 256>>>((const int4*)edst, deg);
    scan1_kernel<<<SCAN_BLOCKS, 256>>>(deg, bsum);
    scan2_kernel<<<1, 256>>>(bsum, bpre, rowptr);
    scan3_kernel<<<SCAN_BLOCKS, 256>>>(deg, bpre, rowptr, cursor, invdeg);
    fill_kernel<<<(NE / 8 + 255) / 256, 256>>>((const int4*)esrc, (const int4*)edst,
                                               cursor, csr);
    cudaEventRecord(g_ev[1], 0);       // CSR ready

    // side: weight prep + fp16 features (independent of CSR chain)
    prep_w_all<<<(3 * DIM * 2 * DIM + 255) / 256, 256, 0, g_side>>>(
        Ws[0], Wn[0], Ws[1], Wn[1], Ws[2], Wn[2], Bt);
    feat_to_h16<<<(NN * DIM / 8 + 255) / 256, 256, 0, g_side>>>(feat, hA);
    cudaEventRecord(g_ev[2], g_side);  // h16 + weights ready

    // joins: main needs h16; side needs CSR
    cudaStreamWaitEvent(0, g_ev[2], 0);
    cudaStreamWaitEvent(g_side, g_ev[1], 0);

    // half-tile geometry
    const int gA_blocks = HALF_ROWS / 8;                 // 3136
    const int gB_blocks = (NN - HALF_ROWS + 7) / 8;      // 3114
    const int mA_blocks = HALF_ROWS / 128;               // 196
    const int mB_blocks = (NN - HALF_ROWS + 127) / 128;  // 195

    __half* cur = hA;
    __half* nxt = hB;
    for (int l = 0; l < 3; ++l) {
        const __half* W = Bt + l * DIM * 2 * DIM;
        // main: gatherA -> (event) -> gemmA
        gather16_kernel<<<gA_blocks, 256>>>(cur, rowptr, csr, invdeg, acc16,
                                            0, HALF_ROWS);
        cudaEventRecord(g_ev[3 + l * 3], 0);
        sage_gemm<<<mA_blocks, 256, SMEM_BYTES>>>(cur, acc16, W, bs[l], nxt, 0);

        // side: after gatherA, gatherB (runs under gemmA) -> gemmB
        cudaStreamWaitEvent(g_side, g_ev[3 + l * 3], 0);
        gather16_kernel<<<gB_blocks, 256, 0, g_side>>>(cur, rowptr, csr, invdeg,
                                                       acc16, HALF_ROWS, NN);
        sage_gemm<<<mB_blocks, 256, SMEM_BYTES, g_side>>>(cur, acc16, W, bs[l],
                                                          nxt, HALF_ROWS);
        cudaEventRecord(g_ev[4 + l * 3], g_side);

        // main: next layer (or pool) needs full nxt
        cudaStreamWaitEvent(0, g_ev[4 + l * 3], 0);

        __half* tmp = cur; cur = nxt; nxt = tmp;
    }

    pool_kernel<<<NG, 512>>>(cur, gids, Wf, bf, out);
}

// round 16
// speedup vs baseline: 1.0850x; 1.0850x over previous
#include <cuda_runtime.h>
#include <cuda_fp16.h>
#include <cstdint>
#include <math.h>

#define NN 50000
#define NE 800000
#define NG 128
#define DIM 128
#define NCLS 10
#define SCAN_BLOCKS 196   // ceil(50000/256)

// ---------------- device scratch ----------------
__device__ __align__(16) __half g_hA[NN * DIM];
__device__ __align__(16) __half g_hB[NN * DIM];
__device__ __align__(16) __half g_acc16[NN * DIM];
__device__ float g_invdeg[NN];
__device__ int g_deg[NN];
__device__ int g_rowptr[NN + 1];
__device__ int g_cursor[NN];
__device__ int g_csr[NE];
__device__ int g_bsum[SCAN_BLOCKS];
// weights transposed+concat fp16 (1-term): [layer][n=128][k=256]
__device__ __align__(16) __half g_Bt[3 * DIM * 2 * DIM];

// ---------------- helpers ----------------
__device__ __forceinline__ uint32_t smem_u32(const void* p) {
    return (uint32_t)__cvta_generic_to_shared((void*)p);
}
__device__ __forceinline__ uint32_t swz(uint32_t x) { return x ^ (((x) >> 3) & 0x70); }

__device__ __forceinline__ void cpa16(uint32_t dst, const void* src, int sz) {
    asm volatile("cp.async.cg.shared.global [%0], [%1], 16, %2;"
                 :: "r"(dst), "l"(src), "r"(sz) : "memory");
}
#define CP_COMMIT() asm volatile("cp.async.commit_group;" ::: "memory")
#define CP_WAIT(n) asm volatile("cp.async.wait_group %0;" :: "n"(n) : "memory")

__device__ __forceinline__ void ldmx4(uint32_t* r, uint32_t a) {
    asm volatile("ldmatrix.sync.aligned.m8n8.x4.shared.b16 {%0,%1,%2,%3}, [%4];"
                 : "=r"(r[0]), "=r"(r[1]), "=r"(r[2]), "=r"(r[3]) : "r"(a));
}
__device__ __forceinline__ void mma16816(float* c, const uint32_t* a, uint32_t b0,
                                         uint32_t b1) {
    asm volatile(
        "mma.sync.aligned.m16n8k16.row.col.f32.f16.f16.f32 "
        "{%0,%1,%2,%3}, {%4,%5,%6,%7}, {%8,%9}, {%0,%1,%2,%3};"
        : "+f"(c[0]), "+f"(c[1]), "+f"(c[2]), "+f"(c[3])
        : "r"(a[0]), "r"(a[1]), "r"(a[2]), "r"(a[3]), "r"(b0), "r"(b1));
}

// ---------------- CSR build ----------------
__global__ void zero_int(int* p, int n) {
    int i = blockIdx.x * blockDim.x + threadIdx.x;
    if (i < n) p[i] = 0;
}
__global__ void hist_kernel(const int4* __restrict__ dst4, int* __restrict__ deg) {
    int tid = blockIdx.x * blockDim.x + threadIdx.x;
    if (tid >= NE / 8) return;
    int4 d0 = __ldg(&dst4[tid * 2]);
    int4 d1 = __ldg(&dst4[tid * 2 + 1]);
    atomicAdd(&deg[d0.x], 1); atomicAdd(&deg[d0.y], 1);
    atomicAdd(&deg[d0.z], 1); atomicAdd(&deg[d0.w], 1);
    atomicAdd(&deg[d1.x], 1); atomicAdd(&deg[d1.y], 1);
    atomicAdd(&deg[d1.z], 1); atomicAdd(&deg[d1.w], 1);
}
__global__ void __launch_bounds__(256)
scan1_kernel(const int* __restrict__ deg, int* __restrict__ bsum) {
    __shared__ int s[256];
    int t = threadIdx.x;
    int idx = blockIdx.x * 256 + t;
    s[t] = (idx < NN) ? deg[idx] : 0;
    __syncthreads();
#pragma unroll
    for (int off = 128; off > 0; off >>= 1) {
        if (t < off) s[t] += s[t + off];
        __syncthreads();
    }
    if (t == 0) bsum[blockIdx.x] = s[0];
}
// scan3 with inlined block-offset computation (replaces scan2):
// each block reduces bsum[0..bid) itself (<=196 ints, L2-hot).
__global__ void __launch_bounds__(256)
scan3_kernel(const int* __restrict__ deg, const int* __restrict__ bsum,
             int* __restrict__ rowptr, int* __restrict__ cursor,
             float* __restrict__ invdeg) {
    __shared__ int s[256];
    __shared__ int boff_sh;
    const int t = threadIdx.x;
    const int bid = blockIdx.x;

    // block offset = sum of bsum[0..bid)
    int acc = (t < bid) ? __ldg(&bsum[t]) : 0;
    s[t] = acc;
    __syncthreads();
#pragma unroll
    for (int off = 128; off > 0; off >>= 1) {
        if (t < off) s[t] += s[t + off];
        __syncthreads();
    }
    if (t == 0) boff_sh = s[0];
    __syncthreads();
    const int boff = boff_sh;
    __syncthreads();

    // local inclusive scan of this block's 256 degrees
    int idx = bid * 256 + t;
    int d = (idx < NN) ? deg[idx] : 0;
    s[t] = d;
    __syncthreads();
#pragma unroll
    for (int off = 1; off < 256; off <<= 1) {
        int u = (t >= off) ? s[t - off] : 0;
        __syncthreads();
        s[t] += u;
        __syncthreads();
    }
    if (idx < NN) {
        int pos = boff + s[t] - d;  // exclusive global prefix
        rowptr[idx] = pos;
        cursor[idx] = pos;
        invdeg[idx] = 1.0f / fmaxf((float)d, 1.0f);
    }
    if (bid == 0 && t == 0) rowptr[NN] = NE;
}
__global__ void fill_kernel(const int4* __restrict__ src4, const int4* __restrict__ dst4,
                            int* __restrict__ cursor, int* __restrict__ csr) {
    int tid = blockIdx.x * blockDim.x + threadIdx.x;
    if (tid >= NE / 8) return;
    int4 d0 = __ldg(&dst4[tid * 2]);
    int4 d1 = __ldg(&dst4[tid * 2 + 1]);
    int4 s0 = __ldg(&src4[tid * 2]);
    int4 s1 = __ldg(&src4[tid * 2 + 1]);
    const int dd[8] = {d0.x, d0.y, d0.z, d0.w, d1.x, d1.y, d1.z, d1.w};
    const int ss[8] = {s0.x, s0.y, s0.z, s0.w, s1.x, s1.y, s1.z, s1.w};
    int pos[8];
#pragma unroll
    for (int i = 0; i < 8; ++i) pos[i] = atomicAdd(&cursor[dd[i]], 1);
#pragma unroll
    for (int i = 0; i < 8; ++i) csr[pos[i]] = ss[i];
}

// ---------------- weight prep: all 3 layers, transpose+concat, fp16 ----------------
__global__ void prep_w_all(const float* __restrict__ Ws0, const float* __restrict__ Wn0,
                           const float* __restrict__ Ws1, const float* __restrict__ Wn1,
                           const float* __restrict__ Ws2, const float* __restrict__ Wn2,
                           __half* __restrict__ Bt) {
    int i = blockIdx.x * blockDim.x + threadIdx.x;
    if (i >= 3 * DIM * 2 * DIM) return;
    int l = i / (DIM * 2 * DIM);
    int r = i - l * (DIM * 2 * DIM);
    int n = r >> 8;
    int k = r & 255;
    const float* Ws = (l == 0) ? Ws0 : (l == 1) ? Ws1 : Ws2;
    const float* Wn = (l == 0) ? Wn0 : (l == 1) ? Wn1 : Wn2;
    float w = (k < DIM) ? Ws[k * DIM + n] : Wn[(k - DIM) * DIM + n];
    Bt[i] = __float2half_rn(w);
}

// ---------------- features -> fp16 ----------------
__global__ void feat_to_h16(const float* __restrict__ f, __half* __restrict__ o) {
    int i = blockIdx.x * blockDim.x + threadIdx.x;  // 8 elems each
    if (i >= NN * DIM / 8) return;
    const float4* p = (const float4*)f + (size_t)i * 2;
    float4 a = p[0], b = p[1];
    uint4 v;
    __half2 t0 = __floats2half2_rn(a.x, a.y);
    __half2 t1 = __floats2half2_rn(a.z, a.w);
    __half2 t2 = __floats2half2_rn(b.x, b.y);
    __half2 t3 = __floats2half2_rn(b.z, b.w);
    v.x = *(uint32_t*)&t0; v.y = *(uint32_t*)&t1;
    v.z = *(uint32_t*)&t2; v.w = *(uint32_t*)&t3;
    *((uint4*)o + i) = v;
}

// ---------------- CSR gather: acc16[n] = fp16(mean_{src in N(n)} h16[src]) ----------------
__global__ void __launch_bounds__(256)
gather16_kernel(const __half* __restrict__ h16, const int* __restrict__ rowptr,
                const int* __restrict__ csr, const float* __restrict__ invdeg,
                __half* __restrict__ acc16) {
    int node = blockIdx.x * 8 + (threadIdx.x >> 5);
    int lane = threadIdx.x & 31;
    if (node >= NN) return;
    int beg = __ldg(&rowptr[node]);
    int end = __ldg(&rowptr[node + 1]);
    float s0 = 0.f, s1 = 0.f, s2 = 0.f, s3 = 0.f;
    int i = beg;
    for (; i + 3 < end; i += 4) {
        int n0 = __ldg(&csr[i]), n1 = __ldg(&csr[i + 1]);
        int n2 = __ldg(&csr[i + 2]), n3 = __ldg(&csr[i + 3]);
        uint2 v0 = *(const uint2*)(h16 + (size_t)n0 * DIM + lane * 4);
        uint2 v1 = *(const uint2*)(h16 + (size_t)n1 * DIM + lane * 4);
        uint2 v2 = *(const uint2*)(h16 + (size_t)n2 * DIM + lane * 4);
        uint2 v3 = *(const uint2*)(h16 + (size_t)n3 * DIM + lane * 4);
#define ACC8(v)                                                     \
        {                                                           \
            float2 fa = __half22float2(*(__half2*)&(v).x);          \
            float2 fb = __half22float2(*(__half2*)&(v).y);          \
            s0 += fa.x; s1 += fa.y; s2 += fb.x; s3 += fb.y;         \
        }
        ACC8(v0) ACC8(v1) ACC8(v2) ACC8(v3)
    }
    for (; i < end; ++i) {
        int n0 = __ldg(&csr[i]);
        uint2 v0 = *(const uint2*)(h16 + (size_t)n0 * DIM + lane * 4);
        ACC8(v0)
    }
#undef ACC8
    float id = invdeg[node];
    __half2 o0 = __floats2half2_rn(s0 * id, s1 * id);
    __half2 o1 = __floats2half2_rn(s2 * id, s3 * id);
    uint2 o;
    o.x = *(uint32_t*)&o0; o.y = *(uint32_t*)&o1;
    *(uint2*)(acc16 + (size_t)node * DIM + lane * 4) = o;
}

// ---------------- fused SAGE GEMM: h16' = fp16(relu([h16|acc16] @ Bt^T + bias)) ----------------
#define SA 0
#define SB 16384
#define SMEM_BYTES 32768

__global__ void __launch_bounds__(256, 2)
sage_gemm(const __half* __restrict__ h16, const __half* __restrict__ acc16,
          const __half* __restrict__ Bt, const float* __restrict__ bias,
          __half* __restrict__ out16) {
    extern __shared__ char sm[];
    const uint32_t sb = smem_u32(sm);
    const int t = threadIdx.x;
    const int lane = t & 31;
    const int wid = t >> 5;
    const int wm = wid & 3;
    const int wn = wid >> 2;
    const int row0 = blockIdx.x * 128;

    float cacc[2][8][4];
#pragma unroll
    for (int a = 0; a < 2; ++a)
#pragma unroll
        for (int b = 0; b < 8; ++b)
#pragma unroll
            for (int c = 0; c < 4; ++c) cacc[a][b][c] = 0.f;

    for (int kc = 0; kc < 4; ++kc) {
        // ---- async stage A + B chunk kc ----
        {
            const __half* Asrc = (kc < 2) ? h16 : acc16;
            const int kbase = (kc & 1) * 64;
#pragma unroll
            for (int u = 0; u < 4; ++u) {
                int li = t + 256 * u;      // 0..1023
                int row = li >> 3, seg = li & 7;
                int r = row0 + row;
                const void* g = Asrc + (size_t)r * DIM + kbase + seg * 8;
                cpa16(sb + SA + swz((uint32_t)(row * 128 + seg * 16)), g,
                      (r < NN) ? 16 : 0);
            }
#pragma unroll
            for (int u = 0; u < 4; ++u) {
                int li = t + 256 * u;
                int row = li >> 3, seg = li & 7;
                size_t gb = (size_t)row * 256 + kc * 64 + seg * 8;
                cpa16(sb + SB + swz((uint32_t)(row * 128 + seg * 16)), Bt + gb, 16);
            }
            CP_COMMIT();
        }
        CP_WAIT(0);
        __syncthreads();

#pragma unroll
        for (int ks = 0; ks < 4; ++ks) {
            uint32_t afr[2][4];
#pragma unroll
            for (int mt = 0; mt < 2; ++mt) {
                uint32_t row = wm * 32 + mt * 16 + (lane & 7) + ((lane >> 3) & 1) * 8;
                uint32_t cb = ks * 32 + ((lane >> 4) & 1) * 16;
                ldmx4(afr[mt], sb + SA + swz(row * 128 + cb));
            }
#pragma unroll
            for (int np = 0; np < 4; ++np) {
                uint32_t nrow = wn * 64 + np * 16 + (lane & 7) + ((lane >> 4) & 1) * 8;
                uint32_t cb = ks * 32 + ((lane >> 3) & 1) * 16;
                uint32_t bh[4];
                ldmx4(bh, sb + SB + swz(nrow * 128 + cb));
#pragma unroll
                for (int mt = 0; mt < 2; ++mt) {
                    mma16816(cacc[mt][2 * np], afr[mt], bh[0], bh[1]);
                    mma16816(cacc[mt][2 * np + 1], afr[mt], bh[2], bh[3]);
                }
            }
        }
        __syncthreads();
    }

    // epilogue: +bias, relu, fp16 store
#pragma unroll
    for (int mt = 0; mt < 2; ++mt) {
        int r0 = row0 + wm * 32 + mt * 16 + (lane >> 2);
#pragma unroll
        for (int nt = 0; nt < 8; ++nt) {
            int c = wn * 64 + nt * 8 + (lane & 3) * 2;
            float b0 = __ldg(&bias[c]);
            float b1 = __ldg(&bias[c + 1]);
            float* cc = cacc[mt][nt];
            if (r0 < NN) {
                __half2 hv = __floats2half2_rn(fmaxf(cc[0] + b0, 0.f),
                                               fmaxf(cc[1] + b1, 0.f));
                *(__half2*)(out16 + (size_t)r0 * DIM + c) = hv;
            }
            int r1 = r0 + 8;
            if (r1 < NN) {
                __half2 hv = __floats2half2_rn(fmaxf(cc[2] + b0, 0.f),
                                               fmaxf(cc[3] + b1, 0.f));
                *(__half2*)(out16 + (size_t)r1 * DIM + c) = hv;
            }
        }
    }
}

// ---------------- mean graph pooling + classifier head ----------------
__global__ void __launch_bounds__(512)
pool_kernel(const __half* __restrict__ h16, const int* __restrict__ gids,
            const float* __restrict__ Wf, const float* __restrict__ bf,
            float* __restrict__ out) {
    __shared__ float part[4][DIM];
    __shared__ float pooled[DIM];
    int g = blockIdx.x;
    int t = threadIdx.x;
    int nl = t >> 7;
    int col = t & 127;

    int lo = 0, hi = NN;
    while (lo < hi) { int m = (lo + hi) >> 1; if (__ldg(&gids[m]) < g) lo = m + 1; else hi = m; }
    int start = lo;
    lo = start; hi = NN;
    while (lo < hi) { int m = (lo + hi) >> 1; if (__ldg(&gids[m]) < g + 1) lo = m + 1; else hi = m; }
    int end = lo;

    float s = 0.f;
    for (int n = start + nl; n < end; n += 4)
        s += __half2float(h16[(size_t)n * DIM + col]);
    part[nl][col] = s;
    __syncthreads();

    if (nl == 0) {
        float cnt = fmaxf((float)(end - start), 1.0f);
        pooled[col] = (part[0][col] + part[1][col] + part[2][col] + part[3][col]) / cnt;
    }
    __syncthreads();

    if (t < NCLS) {
        float o = bf[t];
#pragma unroll 8
        for (int k = 0; k < DIM; ++k) o = fmaf(pooled[k], Wf[k * NCLS + t], o);
        out[g * NCLS + t] = o;
    }
}

// ---------------- launch ----------------
static cudaStream_t g_side = 0;
static cudaEvent_t g_ev0, g_ev1;
static bool g_res_init = false;

extern "C" void kernel_launch(void* const* d_in, const int* in_sizes, int n_in,
                              void* d_out, int out_size) {
    const float* feat = (const float*)d_in[0];
    const int* esrc = (const int*)d_in[1];
    const int* edst = (const int*)d_in[2];
    const int* gids = (const int*)d_in[3];
    const float* Ws[3] = {(const float*)d_in[4], (const float*)d_in[7], (const float*)d_in[10]};
    const float* Wn[3] = {(const float*)d_in[5], (const float*)d_in[8], (const float*)d_in[11]};
    const float* bs[3] = {(const float*)d_in[6], (const float*)d_in[9], (const float*)d_in[12]};
    const float* Wf = (const float*)d_in[13];
    const float* bf = (const float*)d_in[14];
    float* out = (float*)d_out;

    if (!g_res_init) {
        cudaStreamCreateWithFlags(&g_side, cudaStreamNonBlocking);
        cudaEventCreateWithFlags(&g_ev0, cudaEventDisableTiming);
        cudaEventCreateWithFlags(&g_ev1, cudaEventDisableTiming);
        cudaFuncSetAttribute(sage_gemm, cudaFuncAttributeMaxDynamicSharedMemorySize,
                             SMEM_BYTES);
        g_res_init = true;
    }

    __half *hA, *hB, *acc16, *Bt;
    float* invdeg;
    int *deg, *rowptr, *cursor, *csr, *bsum;
    cudaGetSymbolAddress((void**)&hA, g_hA);
    cudaGetSymbolAddress((void**)&hB, g_hB);
    cudaGetSymbolAddress((void**)&acc16, g_acc16);
    cudaGetSymbolAddress((void**)&invdeg, g_invdeg);
    cudaGetSymbolAddress((void**)&deg, g_deg);
    cudaGetSymbolAddress((void**)&rowptr, g_rowptr);
    cudaGetSymbolAddress((void**)&cursor, g_cursor);
    cudaGetSymbolAddress((void**)&csr, g_csr);
    cudaGetSymbolAddress((void**)&bsum, g_bsum);
    cudaGetSymbolAddress((void**)&Bt, g_Bt);

    // fork: side stream branches off main
    cudaEventRecord(g_ev0, 0);
    cudaStreamWaitEvent(g_side, g_ev0, 0);

    // main: CSR build + invdeg chain (scan2 merged into scan3)
    zero_int<<<(NN + 255) / 256, 256>>>(deg, NN);
    hist_kernel<<<(NE / 8 + 255) / 256, 256>>>((const int4*)edst, deg);
    scan1_kernel<<<SCAN_BLOCKS, 256>>>(deg, bsum);
    scan3_kernel<<<SCAN_BLOCKS, 256>>>(deg, bsum, rowptr, cursor, invdeg);
    fill_kernel<<<(NE / 8 + 255) / 256, 256>>>((const int4*)esrc, (const int4*)edst,
                                               cursor, csr);

    // side: weight prep + fp16 features (independent of CSR chain)
    prep_w_all<<<(3 * DIM * 2 * DIM + 255) / 256, 256, 0, g_side>>>(
        Ws[0], Wn[0], Ws[1], Wn[1], Ws[2], Wn[2], Bt);
    feat_to_h16<<<(NN * DIM / 8 + 255) / 256, 256, 0, g_side>>>(feat, hA);
    cudaEventRecord(g_ev1, g_side);

    // join: main needs h16 (and fill, in-stream) before gather0
    cudaStreamWaitEvent(0, g_ev1, 0);

    const int gemm_blocks = (NN + 127) / 128;
    const int gather_blocks = (NN + 7) / 8;

    __half* cur = hA;
    __half* nxt = hB;
    for (int l = 0; l < 3; ++l) {
        gather16_kernel<<<gather_blocks, 256>>>(cur, rowptr, csr, invdeg, acc16);
        sage_gemm<<<gemm_blocks, 256, SMEM_BYTES>>>(cur, acc16,
                                                    Bt + l * DIM * 2 * DIM,
                                                    bs[l], nxt);
        __half* tmp = cur; cur = nxt; nxt = tmp;
    }

    pool_kernel<<<NG, 512>>>(cur, gids, Wf, bf, out);
}

// round 17
// speedup vs baseline: 1.1167x; 1.0292x over previous
#include <cuda_runtime.h>
#include <cuda_fp16.h>
#include <cstdint>
#include <math.h>

#define NN 50000
#define NE 800000
#define NG 128
#define DIM 128
#define NCLS 10
#define SCAN_BLOCKS 196   // ceil(50000/256)

// ---------------- device scratch ----------------
__device__ __align__(16) __half g_hA[NN * DIM];
__device__ __align__(16) __half g_hB[NN * DIM];
__device__ __align__(16) __half g_acc16[NN * DIM];
__device__ float g_invdeg[NN];
__device__ int g_deg[NN];
__device__ int g_rowptr[NN + 1];
__device__ int g_cursor[NN];
__device__ int g_csr[NE];
__device__ int g_bsum[SCAN_BLOCKS];
// weights transposed+concat fp16 (1-term): [layer][n=128][k=256]
__device__ __align__(16) __half g_Bt[3 * DIM * 2 * DIM];

// ---------------- helpers ----------------
__device__ __forceinline__ uint32_t smem_u32(const void* p) {
    return (uint32_t)__cvta_generic_to_shared((void*)p);
}
__device__ __forceinline__ uint32_t swz(uint32_t x) { return x ^ (((x) >> 3) & 0x70); }

__device__ __forceinline__ void cpa16(uint32_t dst, const void* src, int sz) {
    asm volatile("cp.async.cg.shared.global [%0], [%1], 16, %2;"
                 :: "r"(dst), "l"(src), "r"(sz) : "memory");
}
#define CP_COMMIT() asm volatile("cp.async.commit_group;" ::: "memory")
#define CP_WAIT(n) asm volatile("cp.async.wait_group %0;" :: "n"(n) : "memory")

__device__ __forceinline__ void ldmx4(uint32_t* r, uint32_t a) {
    asm volatile("ldmatrix.sync.aligned.m8n8.x4.shared.b16 {%0,%1,%2,%3}, [%4];"
                 : "=r"(r[0]), "=r"(r[1]), "=r"(r[2]), "=r"(r[3]) : "r"(a));
}
__device__ __forceinline__ void mma16816(float* c, const uint32_t* a, uint32_t b0,
                                         uint32_t b1) {
    asm volatile(
        "mma.sync.aligned.m16n8k16.row.col.f32.f16.f16.f32 "
        "{%0,%1,%2,%3}, {%4,%5,%6,%7}, {%8,%9}, {%0,%1,%2,%3};"
        : "+f"(c[0]), "+f"(c[1]), "+f"(c[2]), "+f"(c[3])
        : "r"(a[0]), "r"(a[1]), "r"(a[2]), "r"(a[3]), "r"(b0), "r"(b1));
}

// ---------------- CSR build ----------------
__global__ void zero_int(int* p, int n) {
    int i = blockIdx.x * blockDim.x + threadIdx.x;
    if (i < n) p[i] = 0;
}
__global__ void hist_kernel(const int4* __restrict__ dst4, int* __restrict__ deg) {
    int tid = blockIdx.x * blockDim.x + threadIdx.x;
    if (tid >= NE / 8) return;
    int4 d0 = __ldg(&dst4[tid * 2]);
    int4 d1 = __ldg(&dst4[tid * 2 + 1]);
    atomicAdd(&deg[d0.x], 1); atomicAdd(&deg[d0.y], 1);
    atomicAdd(&deg[d0.z], 1); atomicAdd(&deg[d0.w], 1);
    atomicAdd(&deg[d1.x], 1); atomicAdd(&deg[d1.y], 1);
    atomicAdd(&deg[d1.z], 1); atomicAdd(&deg[d1.w], 1);
}
__global__ void __launch_bounds__(256)
scan1_kernel(const int* __restrict__ deg, int* __restrict__ bsum) {
    __shared__ int s[256];
    int t = threadIdx.x;
    int idx = blockIdx.x * 256 + t;
    s[t] = (idx < NN) ? deg[idx] : 0;
    __syncthreads();
#pragma unroll
    for (int off = 128; off > 0; off >>= 1) {
        if (t < off) s[t] += s[t + off];
        __syncthreads();
    }
    if (t == 0) bsum[blockIdx.x] = s[0];
}
// scan3 with inlined block-offset computation (replaces scan2)
__global__ void __launch_bounds__(256)
scan3_kernel(const int* __restrict__ deg, const int* __restrict__ bsum,
             int* __restrict__ rowptr, int* __restrict__ cursor,
             float* __restrict__ invdeg) {
    __shared__ int s[256];
    __shared__ int boff_sh;
    const int t = threadIdx.x;
    const int bid = blockIdx.x;

    int acc = (t < bid) ? __ldg(&bsum[t]) : 0;
    s[t] = acc;
    __syncthreads();
#pragma unroll
    for (int off = 128; off > 0; off >>= 1) {
        if (t < off) s[t] += s[t + off];
        __syncthreads();
    }
    if (t == 0) boff_sh = s[0];
    __syncthreads();
    const int boff = boff_sh;
    __syncthreads();

    int idx = bid * 256 + t;
    int d = (idx < NN) ? deg[idx] : 0;
    s[t] = d;
    __syncthreads();
#pragma unroll
    for (int off = 1; off < 256; off <<= 1) {
        int u = (t >= off) ? s[t - off] : 0;
        __syncthreads();
        s[t] += u;
        __syncthreads();
    }
    if (idx < NN) {
        int pos = boff + s[t] - d;
        rowptr[idx] = pos;
        cursor[idx] = pos;
        invdeg[idx] = 1.0f / fmaxf((float)d, 1.0f);
    }
    if (bid == 0 && t == 0) rowptr[NN] = NE;
}
__global__ void fill_kernel(const int4* __restrict__ src4, const int4* __restrict__ dst4,
                            int* __restrict__ cursor, int* __restrict__ csr) {
    int tid = blockIdx.x * blockDim.x + threadIdx.x;
    if (tid >= NE / 8) return;
    int4 d0 = __ldg(&dst4[tid * 2]);
    int4 d1 = __ldg(&dst4[tid * 2 + 1]);
    int4 s0 = __ldg(&src4[tid * 2]);
    int4 s1 = __ldg(&src4[tid * 2 + 1]);
    const int dd[8] = {d0.x, d0.y, d0.z, d0.w, d1.x, d1.y, d1.z, d1.w};
    const int ss[8] = {s0.x, s0.y, s0.z, s0.w, s1.x, s1.y, s1.z, s1.w};
    int pos[8];
#pragma unroll
    for (int i = 0; i < 8; ++i) pos[i] = atomicAdd(&cursor[dd[i]], 1);
#pragma unroll
    for (int i = 0; i < 8; ++i) csr[pos[i]] = ss[i];
}

// ---------------- weight prep ----------------
__global__ void prep_w_all(const float* __restrict__ Ws0, const float* __restrict__ Wn0,
                           const float* __restrict__ Ws1, const float* __restrict__ Wn1,
                           const float* __restrict__ Ws2, const float* __restrict__ Wn2,
                           __half* __restrict__ Bt) {
    int i = blockIdx.x * blockDim.x + threadIdx.x;
    if (i >= 3 * DIM * 2 * DIM) return;
    int l = i / (DIM * 2 * DIM);
    int r = i - l * (DIM * 2 * DIM);
    int n = r >> 8;
    int k = r & 255;
    const float* Ws = (l == 0) ? Ws0 : (l == 1) ? Ws1 : Ws2;
    const float* Wn = (l == 0) ? Wn0 : (l == 1) ? Wn1 : Wn2;
    float w = (k < DIM) ? Ws[k * DIM + n] : Wn[(k - DIM) * DIM + n];
    Bt[i] = __float2half_rn(w);
}

// ---------------- features -> fp16 ----------------
__global__ void feat_to_h16(const float* __restrict__ f, __half* __restrict__ o) {
    int i = blockIdx.x * blockDim.x + threadIdx.x;
    if (i >= NN * DIM / 8) return;
    const float4* p = (const float4*)f + (size_t)i * 2;
    float4 a = p[0], b = p[1];
    uint4 v;
    __half2 t0 = __floats2half2_rn(a.x, a.y);
    __half2 t1 = __floats2half2_rn(a.z, a.w);
    __half2 t2 = __floats2half2_rn(b.x, b.y);
    __half2 t3 = __floats2half2_rn(b.z, b.w);
    v.x = *(uint32_t*)&t0; v.y = *(uint32_t*)&t1;
    v.z = *(uint32_t*)&t2; v.w = *(uint32_t*)&t3;
    *((uint4*)o + i) = v;
}

// ---------------- CSR gather ----------------
__global__ void __launch_bounds__(256)
gather16_kernel(const __half* __restrict__ h16, const int* __restrict__ rowptr,
                const int* __restrict__ csr, const float* __restrict__ invdeg,
                __half* __restrict__ acc16) {
    int node = blockIdx.x * 8 + (threadIdx.x >> 5);
    int lane = threadIdx.x & 31;
    if (node >= NN) return;
    int beg = __ldg(&rowptr[node]);
    int end = __ldg(&rowptr[node + 1]);
    float s0 = 0.f, s1 = 0.f, s2 = 0.f, s3 = 0.f;
    int i = beg;
    for (; i + 3 < end; i += 4) {
        int n0 = __ldg(&csr[i]), n1 = __ldg(&csr[i + 1]);
        int n2 = __ldg(&csr[i + 2]), n3 = __ldg(&csr[i + 3]);
        uint2 v0 = *(const uint2*)(h16 + (size_t)n0 * DIM + lane * 4);
        uint2 v1 = *(const uint2*)(h16 + (size_t)n1 * DIM + lane * 4);
        uint2 v2 = *(const uint2*)(h16 + (size_t)n2 * DIM + lane * 4);
        uint2 v3 = *(const uint2*)(h16 + (size_t)n3 * DIM + lane * 4);
#define ACC8(v)                                                     \
        {                                                           \
            float2 fa = __half22float2(*(__half2*)&(v).x);          \
            float2 fb = __half22float2(*(__half2*)&(v).y);          \
            s0 += fa.x; s1 += fa.y; s2 += fb.x; s3 += fb.y;         \
        }
        ACC8(v0) ACC8(v1) ACC8(v2) ACC8(v3)
    }
    for (; i < end; ++i) {
        int n0 = __ldg(&csr[i]);
        uint2 v0 = *(const uint2*)(h16 + (size_t)n0 * DIM + lane * 4);
        ACC8(v0)
    }
#undef ACC8
    float id = invdeg[node];
    __half2 o0 = __floats2half2_rn(s0 * id, s1 * id);
    __half2 o1 = __floats2half2_rn(s2 * id, s3 * id);
    uint2 o;
    o.x = *(uint32_t*)&o0; o.y = *(uint32_t*)&o1;
    *(uint2*)(acc16 + (size_t)node * DIM + lane * 4) = o;
}

// ---------------- fused SAGE GEMM, 2-stage pipelined staging ----------------
#define SA 0
#define SB 16384
#define STAGE 32768
#define SMEM_BYTES 65536

__global__ void __launch_bounds__(256, 2)
sage_gemm(const __half* __restrict__ h16, const __half* __restrict__ acc16,
          const __half* __restrict__ Bt, const float* __restrict__ bias,
          __half* __restrict__ out16) {
    extern __shared__ char sm[];
    const uint32_t sb = smem_u32(sm);
    const int t = threadIdx.x;
    const int lane = t & 31;
    const int wid = t >> 5;
    const int wm = wid & 3;
    const int wn = wid >> 2;
    const int row0 = blockIdx.x * 128;

    float cacc[2][8][4];
#pragma unroll
    for (int a = 0; a < 2; ++a)
#pragma unroll
        for (int b = 0; b < 8; ++b)
#pragma unroll
            for (int c = 0; c < 4; ++c) cacc[a][b][c] = 0.f;

    auto stage = [&](int kc, int s) {
        const __half* Asrc = (kc < 2) ? h16 : acc16;
        const int kbase = (kc & 1) * 64;
        const uint32_t sbase = sb + s * STAGE;
#pragma unroll
        for (int u = 0; u < 4; ++u) {
            int li = t + 256 * u;      // 0..1023
            int row = li >> 3, seg = li & 7;
            int r = row0 + row;
            const void* g = Asrc + (size_t)r * DIM + kbase + seg * 8;
            cpa16(sbase + SA + swz((uint32_t)(row * 128 + seg * 16)), g,
                  (r < NN) ? 16 : 0);
        }
#pragma unroll
        for (int u = 0; u < 4; ++u) {
            int li = t + 256 * u;
            int row = li >> 3, seg = li & 7;
            size_t gb = (size_t)row * 256 + kc * 64 + seg * 8;
            cpa16(sbase + SB + swz((uint32_t)(row * 128 + seg * 16)), Bt + gb, 16);
        }
        CP_COMMIT();
    };

    stage(0, 0);
    for (int kc = 0; kc < 4; ++kc) {
        const int cur = kc & 1;
        if (kc < 3) {
            stage(kc + 1, cur ^ 1);   // async copy of next chunk overlaps MMA below
            CP_WAIT(1);               // chunk kc's copy complete
        } else {
            CP_WAIT(0);
        }
        __syncthreads();

        const uint32_t sbase = sb + cur * STAGE;
#pragma unroll
        for (int ks = 0; ks < 4; ++ks) {
            uint32_t afr[2][4];
#pragma unroll
            for (int mt = 0; mt < 2; ++mt) {
                uint32_t row = wm * 32 + mt * 16 + (lane & 7) + ((lane >> 3) & 1) * 8;
                uint32_t cb = ks * 32 + ((lane >> 4) & 1) * 16;
                ldmx4(afr[mt], sbase + SA + swz(row * 128 + cb));
            }
#pragma unroll
            for (int np = 0; np < 4; ++np) {
                uint32_t nrow = wn * 64 + np * 16 + (lane & 7) + ((lane >> 4) & 1) * 8;
                uint32_t cb = ks * 32 + ((lane >> 3) & 1) * 16;
                uint32_t bh[4];
                ldmx4(bh, sbase + SB + swz(nrow * 128 + cb));
#pragma unroll
                for (int mt = 0; mt < 2; ++mt) {
                    mma16816(cacc[mt][2 * np], afr[mt], bh[0], bh[1]);
                    mma16816(cacc[mt][2 * np + 1], afr[mt], bh[2], bh[3]);
                }
            }
        }
        __syncthreads();
    }

    // epilogue: +bias, relu, fp16 store
#pragma unroll
    for (int mt = 0; mt < 2; ++mt) {
        int r0 = row0 + wm * 32 + mt * 16 + (lane >> 2);
#pragma unroll
        for (int nt = 0; nt < 8; ++nt) {
            int c = wn * 64 + nt * 8 + (lane & 3) * 2;
            float b0 = __ldg(&bias[c]);
            float b1 = __ldg(&bias[c + 1]);
            float* cc = cacc[mt][nt];
            if (r0 < NN) {
                __half2 hv = __floats2half2_rn(fmaxf(cc[0] + b0, 0.f),
                                               fmaxf(cc[1] + b1, 0.f));
                *(__half2*)(out16 + (size_t)r0 * DIM + c) = hv;
            }
            int r1 = r0 + 8;
            if (r1 < NN) {
                __half2 hv = __floats2half2_rn(fmaxf(cc[2] + b0, 0.f),
                                               fmaxf(cc[3] + b1, 0.f));
                *(__half2*)(out16 + (size_t)r1 * DIM + c) = hv;
            }
        }
    }
}

// ---------------- mean graph pooling + classifier head ----------------
__global__ void __launch_bounds__(512)
pool_kernel(const __half* __restrict__ h16, const int* __restrict__ gids,
            const float* __restrict__ Wf, const float* __restrict__ bf,
            float* __restrict__ out) {
    __shared__ float part[4][DIM];
    __shared__ float pooled[DIM];
    int g = blockIdx.x;
    int t = threadIdx.x;
    int nl = t >> 7;
    int col = t & 127;

    int lo = 0, hi = NN;
    while (lo < hi) { int m = (lo + hi) >> 1; if (__ldg(&gids[m]) < g) lo = m + 1; else hi = m; }
    int start = lo;
    lo = start; hi = NN;
    while (lo < hi) { int m = (lo + hi) >> 1; if (__ldg(&gids[m]) < g + 1) lo = m + 1; else hi = m; }
    int end = lo;

    float s = 0.f;
    for (int n = start + nl; n < end; n += 4)
        s += __half2float(h16[(size_t)n * DIM + col]);
    part[nl][col] = s;
    __syncthreads();

    if (nl == 0) {
        float cnt = fmaxf((float)(end - start), 1.0f);
        pooled[col] = (part[0][col] + part[1][col] + part[2][col] + part[3][col]) / cnt;
    }
    __syncthreads();

    if (t < NCLS) {
        float o = bf[t];
#pragma unroll 8
        for (int k = 0; k < DIM; ++k) o = fmaf(pooled[k], Wf[k * NCLS + t], o);
        out[g * NCLS + t] = o;
    }
}

// ---------------- launch ----------------
static cudaStream_t g_side = 0;
static cudaEvent_t g_ev0, g_ev1;
static bool g_res_init = false;

extern "C" void kernel_launch(void* const* d_in, const int* in_sizes, int n_in,
                              void* d_out, int out_size) {
    const float* feat = (const float*)d_in[0];
    const int* esrc = (const int*)d_in[1];
    const int* edst = (const int*)d_in[2];
    const int* gids = (const int*)d_in[3];
    const float* Ws[3] = {(const float*)d_in[4], (const float*)d_in[7], (const float*)d_in[10]};
    const float* Wn[3] = {(const float*)d_in[5], (const float*)d_in[8], (const float*)d_in[11]};
    const float* bs[3] = {(const float*)d_in[6], (const float*)d_in[9], (const float*)d_in[12]};
    const float* Wf = (const float*)d_in[13];
    const float* bf = (const float*)d_in[14];
    float* out = (float*)d_out;

    if (!g_res_init) {
        cudaStreamCreateWithFlags(&g_side, cudaStreamNonBlocking);
        cudaEventCreateWithFlags(&g_ev0, cudaEventDisableTiming);
        cudaEventCreateWithFlags(&g_ev1, cudaEventDisableTiming);
        cudaFuncSetAttribute(sage_gemm, cudaFuncAttributeMaxDynamicSharedMemorySize,
                             SMEM_BYTES);
        g_res_init = true;
    }

    __half *hA, *hB, *acc16, *Bt;
    float* invdeg;
    int *deg, *rowptr, *cursor, *csr, *bsum;
    cudaGetSymbolAddress((void**)&hA, g_hA);
    cudaGetSymbolAddress((void**)&hB, g_hB);
    cudaGetSymbolAddress((void**)&acc16, g_acc16);
    cudaGetSymbolAddress((void**)&invdeg, g_invdeg);
    cudaGetSymbolAddress((void**)&deg, g_deg);
    cudaGetSymbolAddress((void**)&rowptr, g_rowptr);
    cudaGetSymbolAddress((void**)&cursor, g_cursor);
    cudaGetSymbolAddress((void**)&csr, g_csr);
    cudaGetSymbolAddress((void**)&bsum, g_bsum);
    cudaGetSymbolAddress((void**)&Bt, g_Bt);

    // fork: side stream branches off main
    cudaEventRecord(g_ev0, 0);
    cudaStreamWaitEvent(g_side, g_ev0, 0);

    // main: CSR build + invdeg chain
    zero_int<<<(NN + 255) / 256, 256>>>(deg, NN);
    hist_kernel<<<(NE / 8 + 255) / 256, 256>>>((const int4*)edst, deg);
    scan1_kernel<<<SCAN_BLOCKS, 256>>>(deg, bsum);
    scan3_kernel<<<SCAN_BLOCKS, 256>>>(deg, bsum, rowptr, cursor, invdeg);
    fill_kernel<<<(NE / 8 + 255) / 256, 256>>>((const int4*)esrc, (const int4*)edst,
                                               cursor, csr);

    // side: weight prep + fp16 features
    prep_w_all<<<(3 * DIM * 2 * DIM + 255) / 256, 256, 0, g_side>>>(
        Ws[0], Wn[0], Ws[1], Wn[1], Ws[2], Wn[2], Bt);
    feat_to_h16<<<(NN * DIM / 8 + 255) / 256, 256, 0, g_side>>>(feat, hA);
    cudaEventRecord(g_ev1, g_side);

    // join
    cudaStreamWaitEvent(0, g_ev1, 0);

    const int gemm_blocks = (NN + 127) / 128;
    const int gather_blocks = (NN + 7) / 8;

    __half* cur = hA;
    __half* nxt = hB;
    for (int l = 0; l < 3; ++l) {
        gather16_kernel<<<gather_blocks, 256>>>(cur, rowptr, csr, invdeg, acc16);
        sage_gemm<<<gemm_blocks, 256, SMEM_BYTES>>>(cur, acc16,
                                                    Bt + l * DIM * 2 * DIM,
                                                    bs[l], nxt);
        __half* tmp = cur; cur = nxt; nxt = tmp;
    }

    pool_kernel<<<NG, 512>>>(cur, gids, Wf, bf, out);
}